// round 1
// baseline (speedup 1.0000x reference)
#include <cuda_runtime.h>

#define BSZ  1024
#define SLEN 512
#define TT   64
#define NW   4   // warps (=chains) per block

__device__ double g_res[BSZ];
__device__ int    g_cnt[BSZ];

static __device__ __forceinline__ unsigned long long pk2(float x, float y) {
    unsigned long long r;
    asm("mov.b64 %0, {%1, %2};" : "=l"(r) : "f"(x), "f"(y));
    return r;
}
static __device__ __forceinline__ float2 upk2(unsigned long long v) {
    float2 r;
    asm("mov.b64 {%0, %1}, %2;" : "=f"(r.x), "=f"(r.y) : "l"(v));
    return r;
}
// Packed fp32x2 FMA (Blackwell): d = a*b + c on both lanes -> SASS FFMA2
static __device__ __forceinline__ unsigned long long ffma2(unsigned long long a,
                                                           unsigned long long b,
                                                           unsigned long long c) {
    unsigned long long d;
    asm("fma.rn.f32x2 %0, %1, %2, %3;" : "=l"(d) : "l"(a), "l"(b), "l"(c));
    return d;
}
static __device__ __forceinline__ unsigned long long fadd2(unsigned long long a,
                                                           unsigned long long b) {
    unsigned long long d;
    asm("add.rn.f32x2 %0, %1, %2;" : "=l"(d) : "l"(a), "l"(b));
    return d;
}

__global__ __launch_bounds__(NW * 32, 2)
void crf_forward(const float* __restrict__ e, const int* __restrict__ tags,
                 const unsigned char* __restrict__ mask,
                 const float* __restrict__ st, const float* __restrict__ et,
                 const float* __restrict__ tmat)
{
    // duplicated-p arrays, double buffered per warp: pd[w][buf][i] = (p_i, p_i)
    __shared__ __align__(16) unsigned long long pd[NW][2][TT];

    const int w     = threadIdx.x >> 5;
    const int lane  = threadIdx.x & 31;
    const int chain = blockIdx.x * NW + w;
    const int j0 = lane, j1 = lane + 32;

    const float*         eb = e    + (size_t)chain * (SLEN * TT);
    const int*           tb = tags + chain * SLEN;
    const unsigned char* mb = mask + chain * SLEN;

    // ---- exp(transition) in registers: lane holds columns j0 and j1 packed ----
    unsigned long long Ep[TT];
#pragma unroll
    for (int i = 0; i < TT; ++i) {
        float a = __expf(__ldg(&tmat[i * TT + j0]));
        float b = __expf(__ldg(&tmat[i * TT + j1]));
        Ep[i] = pk2(a, b);
    }

    // ---- tag-path score + mask count (gathers, lanes stride over s) ----
    float scp = 0.f;
    int cntp = 0;
#pragma unroll 1
    for (int s = lane; s < SLEN; s += 32) {
        int m = mb[s];
        cntp += m;
        if (s > 0 && m) {
            int tp = tb[s - 1], tn = tb[s];
            scp += __ldg(&tmat[tp * TT + tn]) + eb[s * TT + tn];
        }
    }
#pragma unroll
    for (int off = 16; off; off >>= 1) {
        scp  += __shfl_xor_sync(0xffffffffu, scp, off);
        cntp += __shfl_xor_sync(0xffffffffu, cntp, off);
    }
    int   t0    = tb[0];
    int   tlast = tb[cntp - 1];
    float score = scp + st[t0] + eb[t0] + et[tlast];

    // ---- forward-vector init (step 0) ----
    float n0 = st[j0] + eb[j0];
    float n1 = st[j1] + eb[j1];
    float base = fmaxf(n0, n1);
#pragma unroll
    for (int off = 16; off; off >>= 1)
        base = fmaxf(base, __shfl_xor_sync(0xffffffffu, base, off));
    float p0 = __expf(n0 - base);
    float p1 = __expf(n1 - base);
    pd[w][0][j0] = pk2(p0, p0);
    pd[w][0][j1] = pk2(p1, p1);
    int cur  = 0;
    int Eacc = 0;   // accumulated power-of-two scale (exact)
    __syncwarp();

    // one recursion step: q = (p . E) * exp(e_s), renormalize by 2^k
    auto do_step = [&](float e0, float e1, int mk) {
        if (!mk) return;
        float F0 = __expf(e0);
        float F1 = __expf(e1);
        const ulonglong2* rp = reinterpret_cast<const ulonglong2*>(pd[w][cur]);
        unsigned long long a0 = 0ull, a1 = 0ull, a2 = 0ull, a3 = 0ull;
#pragma unroll
        for (int k = 0; k < 32; k += 2) {
            ulonglong2 v0 = rp[k];
            ulonglong2 v1 = rp[k + 1];
            a0 = ffma2(v0.x, Ep[2 * k],     a0);
            a1 = ffma2(v0.y, Ep[2 * k + 1], a1);
            a2 = ffma2(v1.x, Ep[2 * k + 2], a2);
            a3 = ffma2(v1.y, Ep[2 * k + 3], a3);
        }
        float2 q = upk2(fadd2(fadd2(a0, a1), fadd2(a2, a3)));
        float q0 = q.x * F0;
        float q1 = q.y * F1;
        float loc = fmaxf(q0, q1);
#pragma unroll
        for (int off = 16; off; off >>= 1)
            loc = fmaxf(loc, __shfl_xor_sync(0xffffffffu, loc, off));
        int ke = (__float_as_int(loc) >> 23) - 127;    // floor(log2(max q))
        Eacc += ke;
        float rinv = __int_as_float((127 - ke) << 23); // exact 2^-ke
        p0 = q0 * rinv;
        p1 = q1 * rinv;
        cur ^= 1;
        pd[w][cur][j0] = pk2(p0, p0);
        pd[w][cur][j1] = pk2(p1, p1);
        __syncwarp();
    };

    // ---- main loop, software prefetch distance 2 ----
    float A0 = eb[1 * TT + j0], A1 = eb[1 * TT + j1]; int Am = mb[1];
    float B0 = eb[2 * TT + j0], B1 = eb[2 * TT + j1]; int Bm = mb[2];
#pragma unroll 1
    for (int s = 1; s < SLEN; s += 2) {
        float e0 = A0, e1 = A1; int mk = Am;
        int sp = s + 2;
        if (sp < SLEN) { A0 = eb[sp * TT + j0]; A1 = eb[sp * TT + j1]; Am = mb[sp]; }
        do_step(e0, e1, mk);
        if (s + 1 < SLEN) {
            float f0 = B0, f1 = B1; int mk2 = Bm;
            int sq = s + 3;
            if (sq < SLEN) { B0 = eb[sq * TT + j0]; B1 = eb[sq * TT + j1]; Bm = mb[sq]; }
            do_step(f0, f1, mk2);
        }
    }

    // ---- logZ and per-chain result ----
    float z = p0 * __expf(et[j0]) + p1 * __expf(et[j1]);
#pragma unroll
    for (int off = 16; off; off >>= 1)
        z += __shfl_xor_sync(0xffffffffu, z, off);
    if (lane == 0) {
        double logZ = (double)base + (double)Eacc * 0.6931471805599453094
                    + log((double)z);
        g_res[chain] = (double)score - logZ;
        g_cnt[chain] = cntp;
    }
}

__global__ void crf_reduce(float* __restrict__ out)
{
    __shared__ double sd[BSZ];
    __shared__ int    si[BSZ];
    int tid = threadIdx.x;
    sd[tid] = g_res[tid];
    si[tid] = g_cnt[tid];
    __syncthreads();
#pragma unroll
    for (int o = BSZ / 2; o > 0; o >>= 1) {
        if (tid < o) { sd[tid] += sd[tid + o]; si[tid] += si[tid + o]; }
        __syncthreads();
    }
    if (tid == 0) out[0] = (float)(sd[0] / (double)si[0]);
}

extern "C" void kernel_launch(void* const* d_in, const int* in_sizes, int n_in,
                              void* d_out, int out_size)
{
    const float*         e    = (const float*)d_in[0];
    const int*           tags = (const int*)d_in[1];
    const unsigned char* mask = (const unsigned char*)d_in[2];
    const float*         st   = (const float*)d_in[3];
    const float*         et   = (const float*)d_in[4];
    const float*         t    = (const float*)d_in[5];

    crf_forward<<<BSZ / NW, NW * 32>>>(e, tags, mask, st, et, t);
    crf_reduce<<<1, BSZ>>>((float*)d_out);
}